// round 7
// baseline (speedup 1.0000x reference)
#include <cuda_runtime.h>

#define Hdim 64
#define Nn   100000
#define Ee   1000000
#define Gg   64

typedef unsigned long long u64;

// ---------------- scratch (static device arrays: no allocation) ----------------
__device__ float g_aggsum[Nn * Hdim];
__device__ float g_aggcnt[Nn];
__device__ float g_gsum[Gg * Hdim];
__device__ float g_gcnt[Gg];

// ---------------- packed f32x2 helpers ----------------
__device__ __forceinline__ u64 bcast2(float x) {
    u64 r; unsigned xi = __float_as_uint(x);
    asm("mov.b64 %0, {%1, %2};" : "=l"(r) : "r"(xi), "r"(xi));
    return r;
}
__device__ __forceinline__ void ffma2(u64& d, u64 a, u64 b) {
    asm("fma.rn.f32x2 %0, %1, %2, %0;" : "+l"(d) : "l"(a), "l"(b));
}
__device__ __forceinline__ float2 unpack2(u64 v) {
    unsigned lo, hi;
    asm("mov.b64 {%0, %1}, %2;" : "=r"(lo), "=r"(hi) : "l"(v));
    return make_float2(__uint_as_float(lo), __uint_as_float(hi));
}
__device__ __forceinline__ float fsel(float4 v, int i) {
    return i == 0 ? v.x : (i == 1 ? v.y : (i == 2 ? v.z : v.w));
}

// ---------------- helpers ----------------
__device__ __forceinline__ float gelu_f(float v) {
    return 0.5f * v * (1.0f + erff(v * 0.7071067811865476f));
}

__device__ __forceinline__ void zero4(u64 (&a)[2][2]) {
    a[0][0] = 0ULL; a[0][1] = 0ULL; a[1][0] = 0ULL; a[1][1] = 0ULL;
}

template <int NT>
__device__ __forceinline__ void cp_smem(float* dst, const float* src, int nfloats, int tid) {
    const float4* s4 = (const float4*)src;
    float4* d4 = (float4*)dst;
    for (int i = tid; i < (nfloats >> 2); i += NT) d4[i] = s4[i];
}

// type-A GEMM (2i x 4j packed): X k-major in smem, stride 68, e-index XOR-swizzled
template <int K, int KB>
__device__ __forceinline__ void gemmA2(const float* __restrict__ Xs, const float* __restrict__ Ws,
                                       int i2, int j4, u64 (&a)[2][2]) {
#pragma unroll 4
    for (int k = 0; k < K; ++k) {
        int kk = KB + k;
        float2 xv = *(const float2*)(Xs + kk * 68 + (i2 ^ (((kk >> 6) & 3) << 3)));
        ulonglong2 wv = *(const ulonglong2*)(Ws + k * 64 + j4);
        u64 x0 = bcast2(xv.x), x1 = bcast2(xv.y);
        ffma2(a[0][0], x0, wv.x); ffma2(a[0][1], x0, wv.y);
        ffma2(a[1][0], x1, wv.x); ffma2(a[1][1], x1, wv.y);
    }
}

// type-B GEMM (2i x 4j packed): H row-major in smem (stride 68), float4 loads along k
template <int K>
__device__ __forceinline__ void gemmB2(const float* __restrict__ Hs, const float* __restrict__ Ws,
                                       int i2, int j4, u64 (&a)[2][2]) {
#pragma unroll 2
    for (int k0 = 0; k0 < K; k0 += 4) {
        float4 h0 = *(const float4*)(Hs + (i2 + 0) * 68 + k0);
        float4 h1 = *(const float4*)(Hs + (i2 + 1) * 68 + k0);
#pragma unroll
        for (int dk = 0; dk < 4; ++dk) {
            ulonglong2 wv = *(const ulonglong2*)(Ws + (k0 + dk) * 64 + j4);
            u64 x0 = bcast2(fsel(h0, dk));
            u64 x1 = bcast2(fsel(h1, dk));
            ffma2(a[0][0], x0, wv.x); ffma2(a[0][1], x0, wv.y);
            ffma2(a[1][0], x1, wv.x); ffma2(a[1][1], x1, wv.y);
        }
    }
}

// bias + exact GELU, store row-major into H (stride 68)
__device__ __forceinline__ void storeH2(float* __restrict__ Hs, int i2, int j4,
                                        u64 (&a)[2][2], const float* __restrict__ bias) {
    float4 b = *(const float4*)(bias + j4);
#pragma unroll
    for (int r = 0; r < 2; ++r) {
        float2 p0 = unpack2(a[r][0]);
        float2 p1 = unpack2(a[r][1]);
        float* row = Hs + (i2 + r) * 68 + j4;
        row[0] = gelu_f(p0.x + b.x);
        row[1] = gelu_f(p0.y + b.y);
        row[2] = gelu_f(p1.x + b.z);
        row[3] = gelu_f(p1.y + b.w);
    }
}

// per-row LayerNorm stats over 64 cols of row-major H
__device__ __forceinline__ void ln_stats(const float* __restrict__ Hs, float* __restrict__ st, int tid) {
    if (tid < 64) {
        float s = 0.0f, s2 = 0.0f;
#pragma unroll
        for (int c = 0; c < 16; ++c) {
            float4 v = *(const float4*)(Hs + tid * 68 + 4 * c);
            s += v.x + v.y + v.z + v.w;
            s2 += v.x * v.x + v.y * v.y + v.z * v.z + v.w * v.w;
        }
        float m = s * (1.0f / 64.0f);
        float var = s2 * (1.0f / 64.0f) - m * m;
        st[tid] = m;
        st[64 + tid] = rsqrtf(fmaxf(var, 0.0f) + 1e-5f);
    }
}

__device__ __forceinline__ void red_v4(float* p, float4 v) {
    asm volatile("red.global.add.v4.f32 [%0], {%1,%2,%3,%4};"
                 :: "l"(p), "f"(v.x), "f"(v.y), "f"(v.z), "f"(v.w) : "memory");
}

// ---------------- zero scratch ----------------
__global__ void zero_kernel() {
    int total = Nn * Hdim + Nn + Gg * Hdim + Gg;
    for (int i = blockIdx.x * blockDim.x + threadIdx.x; i < total; i += gridDim.x * blockDim.x) {
        if (i < Nn * Hdim) g_aggsum[i] = 0.0f;
        else if (i < Nn * Hdim + Nn) g_aggcnt[i - Nn * Hdim] = 0.0f;
        else if (i < Nn * Hdim + Nn + Gg * Hdim) g_gsum[i - Nn * Hdim - Nn] = 0.0f;
        else g_gcnt[i - Nn * Hdim - Nn - Gg * Hdim] = 0.0f;
    }
}

// ---------------- kernel 1: fused edge MLP + message MLP + scatter (512 thr) ----------------
#define E_OW1 0
#define E_OW2 16384
#define E_ON1 20480
#define E_ON2 28672
#define E_OB  32768
#define E_OX  33280
#define E_OH  50688
#define E_OST 55040
#define E_OROW 55168
#define E_SMEM_BYTES (55232 * 4)

__global__ __launch_bounds__(512, 1) void edge_node1_kernel(
    const float* __restrict__ x, const int* __restrict__ ei,
    const float* __restrict__ ea, const float* __restrict__ u,
    const int* __restrict__ batch,
    const float* __restrict__ eW1, const float* __restrict__ eb1,
    const float* __restrict__ eW2, const float* __restrict__ eb2,
    const float* __restrict__ egm, const float* __restrict__ ebt,
    const float* __restrict__ nW1, const float* __restrict__ nb1,
    const float* __restrict__ nW2, const float* __restrict__ nb2,
    const float* __restrict__ ngm, const float* __restrict__ nbt,
    float* __restrict__ edge_out) {
    extern __shared__ float sm[];
    int tid = threadIdx.x;
    cp_smem<512>(sm + E_OW1, eW1, 16384, tid);
    cp_smem<512>(sm + E_OW2, eW2, 4096, tid);
    cp_smem<512>(sm + E_ON1, nW1, 8192, tid);
    cp_smem<512>(sm + E_ON2, nW2, 4096, tid);
    if (tid < 64) {
        sm[E_OB + tid] = eb1[tid];       sm[E_OB + 64 + tid] = eb2[tid];
        sm[E_OB + 128 + tid] = egm[tid]; sm[E_OB + 192 + tid] = ebt[tid];
        sm[E_OB + 256 + tid] = nb1[tid]; sm[E_OB + 320 + tid] = nb2[tid];
        sm[E_OB + 384 + tid] = ngm[tid]; sm[E_OB + 448 + tid] = nbt[tid];
    }
    __syncthreads();

    const int i2 = (tid >> 4) << 1;       // 32 groups * 2 rows = 64 edges
    const int j4 = (tid & 15) << 2;       // 16 groups * 4 cols = 64 outs
    int* srow = (int*)(sm + E_OROW);

    for (int t = blockIdx.x; t < Ee / 64; t += gridDim.x) {
        // -------- gather: [x[row] | x[col] | edge_attr | u[batch[row]]] k-major, swizzled
        {
            int seg = tid >> 7;           // 0..3
            int e = (tid >> 1) & 63;      // 0..63
            int sub = tid & 1;            // 0..1
            int eg_ = t * 64 + e;
            int row = ei[eg_];
            const float* src;
            if (seg == 0) {
                src = x + (size_t)row * 64;
                if (sub == 0) {
                    srow[e] = row;
                    atomicAdd(&g_aggcnt[row], 1.0f);
                }
            } else if (seg == 1) {
                int col = ei[Ee + eg_];
                src = x + (size_t)col * 64;
            } else if (seg == 2) {
                src = ea + (size_t)eg_ * 64;
            } else {
                int b = batch[row];
                src = u + (size_t)b * 64;
            }
            int ep = e ^ (seg << 3);
            float* dst = sm + E_OX + seg * 64 * 68 + ep;
            const float4* s4 = (const float4*)src;
#pragma unroll
            for (int tt = sub * 8; tt < sub * 8 + 8; ++tt) {
                float4 v = s4[tt];
                float* d = dst + tt * 4 * 68;
                d[0] = v.x; d[68] = v.y; d[136] = v.z; d[204] = v.w;
            }
        }
        __syncthreads();

        u64 acc[2][2];
        // edge MLP layer 1 (K=256)
        zero4(acc);
        gemmA2<256, 0>(sm + E_OX, sm + E_OW1, i2, j4, acc);
        storeH2(sm + E_OH, i2, j4, acc, sm + E_OB + 0);
        __syncthreads();
        // edge MLP layer 2 (K=64)
        zero4(acc);
        gemmB2<64>(sm + E_OH, sm + E_OW2, i2, j4, acc);
        __syncthreads();
        storeH2(sm + E_OH, i2, j4, acc, sm + E_OB + 64);
        __syncthreads();
        ln_stats(sm + E_OH, sm + E_OST, tid);
        __syncthreads();
        // LN -> edge_attr_new: write global + place into sX rows 128..191 (swizzle 16)
        {
            int j = tid & 63, g2 = tid >> 6;   // g2: 0..7
            float gj = sm[E_OB + 128 + j], bj = sm[E_OB + 192 + j];
            float* ebase = edge_out + (size_t)t * 64 * 64;
#pragma unroll
            for (int r = 0; r < 8; ++r) {
                int e = g2 * 8 + r;
                float v = sm[E_OH + e * 68 + j];
                float nv = (v - sm[E_OST + e]) * sm[E_OST + 64 + e] * gj + bj;
                sm[E_OX + (128 + j) * 68 + (e ^ 16)] = nv;
                ebase[(size_t)e * 64 + j] = nv;
            }
        }
        __syncthreads();
        // message MLP layer 1: input = sX rows 64..191 = [x[col] | edge_attr_new] (K=128)
        zero4(acc);
        gemmA2<128, 64>(sm + E_OX, sm + E_ON1, i2, j4, acc);
        storeH2(sm + E_OH, i2, j4, acc, sm + E_OB + 256);
        __syncthreads();
        // message MLP layer 2 (K=64)
        zero4(acc);
        gemmB2<64>(sm + E_OH, sm + E_ON2, i2, j4, acc);
        __syncthreads();
        storeH2(sm + E_OH, i2, j4, acc, sm + E_OB + 320);
        __syncthreads();
        ln_stats(sm + E_OH, sm + E_OST, tid);
        __syncthreads();
        // LN + vectorized scatter-add into aggsum[row]
        {
            float4 g4 = *(const float4*)(sm + E_OB + 384 + j4);
            float4 b4 = *(const float4*)(sm + E_OB + 448 + j4);
#pragma unroll
            for (int ebk = 0; ebk < 2; ++ebk) {
                int e = (tid >> 4) + (ebk << 5);   // 0..31, 32..63
                float mn = sm[E_OST + e], rs = sm[E_OST + 64 + e];
                float4 v = *(const float4*)(sm + E_OH + e * 68 + j4);
                v.x = (v.x - mn) * rs * g4.x + b4.x;
                v.y = (v.y - mn) * rs * g4.y + b4.y;
                v.z = (v.z - mn) * rs * g4.z + b4.z;
                v.w = (v.w - mn) * rs * g4.w + b4.w;
                red_v4(g_aggsum + (size_t)srow[e] * 64 + j4, v);
            }
        }
        __syncthreads();
    }
}

// ---------------- kernel 2: node update MLP + graph scatter (512 thr, 2 CTA/SM) ----------------
#define N_OW1 0
#define N_OW2 8192
#define N_OB  12288
#define N_OX  12544
#define N_OH  21248
#define N_OST 25600
#define N_OBI 25728
#define N_SMEM_BYTES (25792 * 4)

__global__ __launch_bounds__(512, 2) void node2_kernel(
    const float* __restrict__ u, const int* __restrict__ batch,
    const float* __restrict__ W1, const float* __restrict__ b1,
    const float* __restrict__ W2, const float* __restrict__ b2,
    const float* __restrict__ gm, const float* __restrict__ bt,
    float* __restrict__ x_out) {
    extern __shared__ float sm[];
    int tid = threadIdx.x;
    cp_smem<512>(sm + N_OW1, W1, 8192, tid);
    cp_smem<512>(sm + N_OW2, W2, 4096, tid);
    if (tid < 64) {
        sm[N_OB + tid] = b1[tid];       sm[N_OB + 64 + tid] = b2[tid];
        sm[N_OB + 128 + tid] = gm[tid]; sm[N_OB + 192 + tid] = bt[tid];
    }
    __syncthreads();
    const int i2 = (tid >> 4) << 1;
    const int j4 = (tid & 15) << 2;
    int* sbi = (int*)(sm + N_OBI);
    const int nTiles = (Nn + 63) / 64;

    for (int t = blockIdx.x; t < nTiles; t += gridDim.x) {
        {
            int e = tid >> 3, q = tid & 7;   // 64 nodes, 8 threads each, 16 floats each
            int n = t * 64 + e;
            bool valid = n < Nn;
            int b = valid ? batch[n] : 0;
            if (q == 0) {
                sbi[e] = b;
                if (valid) atomicAdd(&g_gcnt[b], 1.0f);
            }
            float inv = valid ? 1.0f / fmaxf(g_aggcnt[n], 1.0f) : 1.0f;
#pragma unroll
            for (int tt = 0; tt < 4; ++tt) {
                int k0 = q * 16 + tt * 4;
                float4 v = make_float4(0.f, 0.f, 0.f, 0.f);
                if (valid) {
                    if (k0 < 64) {
                        v = ((const float4*)(g_aggsum + (size_t)n * 64))[k0 >> 2];
                        v.x *= inv; v.y *= inv; v.z *= inv; v.w *= inv;
                    } else {
                        v = ((const float4*)(u + (size_t)b * 64))[(k0 - 64) >> 2];
                    }
                }
                int ep = e ^ ((k0 >> 6) << 3);
                float* d = sm + N_OX + k0 * 68 + ep;
                d[0] = v.x; d[68] = v.y; d[136] = v.z; d[204] = v.w;
            }
        }
        __syncthreads();
        u64 acc[2][2];
        zero4(acc);
        gemmA2<128, 0>(sm + N_OX, sm + N_OW1, i2, j4, acc);
        storeH2(sm + N_OH, i2, j4, acc, sm + N_OB);
        __syncthreads();
        zero4(acc);
        gemmB2<64>(sm + N_OH, sm + N_OW2, i2, j4, acc);
        __syncthreads();
        storeH2(sm + N_OH, i2, j4, acc, sm + N_OB + 64);
        __syncthreads();
        ln_stats(sm + N_OH, sm + N_OST, tid);
        __syncthreads();
        {
            int j = tid & 63, g2 = tid >> 6;
            float gj = sm[N_OB + 128 + j], bj = sm[N_OB + 192 + j];
#pragma unroll
            for (int r = 0; r < 8; ++r) {
                int e = g2 * 8 + r;
                int n = t * 64 + e;
                float v = sm[N_OH + e * 68 + j];
                float nv = (v - sm[N_OST + e]) * sm[N_OST + 64 + e] * gj + bj;
                sm[N_OH + e * 68 + j] = nv;  // in-place: same (e,j) owner
                if (n < Nn) x_out[(size_t)n * 64 + j] = nv;
            }
        }
        __syncthreads();
        {
#pragma unroll
            for (int ebk = 0; ebk < 2; ++ebk) {
                int e = (tid >> 4) + (ebk << 5);
                int n = t * 64 + e;
                if (n < Nn) {
                    float4 v = *(const float4*)(sm + N_OH + e * 68 + j4);
                    red_v4(g_gsum + (size_t)sbi[e] * 64 + j4, v);
                }
            }
        }
        __syncthreads();
    }
}

// ---------------- kernel 3: global MLP (512 thr) ----------------
__global__ __launch_bounds__(512, 1) void glob_kernel(
    const float* __restrict__ u,
    const float* __restrict__ W1, const float* __restrict__ b1,
    const float* __restrict__ W2, const float* __restrict__ b2,
    const float* __restrict__ gm, const float* __restrict__ bt,
    float* __restrict__ u_out) {
    extern __shared__ float sm[];
    int tid = threadIdx.x;
    cp_smem<512>(sm + N_OW1, W1, 8192, tid);
    cp_smem<512>(sm + N_OW2, W2, 4096, tid);
    if (tid < 64) {
        sm[N_OB + tid] = b1[tid];       sm[N_OB + 64 + tid] = b2[tid];
        sm[N_OB + 128 + tid] = gm[tid]; sm[N_OB + 192 + tid] = bt[tid];
    }
    __syncthreads();
    const int i2 = (tid >> 4) << 1;   // 32 groups * 2 rows = 64 graphs
    const int j4 = (tid & 15) << 2;
    {
        int e = tid >> 3, q = tid & 7;   // 64 graphs, 8 threads each, 16 floats each
        float inv = 1.0f / fmaxf(g_gcnt[e], 1.0f);
#pragma unroll
        for (int tt = 0; tt < 4; ++tt) {
            int k0 = q * 16 + tt * 4;
            float4 v;
            if (k0 < 64) {
                v = ((const float4*)(u + (size_t)e * 64))[k0 >> 2];
            } else {
                v = ((const float4*)(g_gsum + (size_t)e * 64))[(k0 - 64) >> 2];
                v.x *= inv; v.y *= inv; v.z *= inv; v.w *= inv;
            }
            int ep = e ^ ((k0 >> 6) << 3);
            float* d = sm + N_OX + k0 * 68 + ep;
            d[0] = v.x; d[68] = v.y; d[136] = v.z; d[204] = v.w;
        }
    }
    __syncthreads();
    u64 acc[2][2];
    zero4(acc);
    gemmA2<128, 0>(sm + N_OX, sm + N_OW1, i2, j4, acc);
    storeH2(sm + N_OH, i2, j4, acc, sm + N_OB);
    __syncthreads();
    zero4(acc);
    gemmB2<64>(sm + N_OH, sm + N_OW2, i2, j4, acc);
    __syncthreads();
    storeH2(sm + N_OH, i2, j4, acc, sm + N_OB + 64);
    __syncthreads();
    ln_stats(sm + N_OH, sm + N_OST, tid);
    __syncthreads();
    {
        int j = tid & 63, g2 = tid >> 6;   // g2: 0..7
        float gj = sm[N_OB + 128 + j], bj = sm[N_OB + 192 + j];
#pragma unroll
        for (int r = 0; r < 8; ++r) {
            int e = g2 * 8 + r;
            float v = sm[N_OH + e * 68 + j];
            float nv = (v - sm[N_OST + e]) * sm[N_OST + 64 + e] * gj + bj;
            u_out[(size_t)e * 64 + j] = nv;
        }
    }
}

// ---------------- launch ----------------
extern "C" void kernel_launch(void* const* d_in, const int* in_sizes, int n_in,
                              void* d_out, int out_size) {
    const float* x = (const float*)d_in[0];
    const int* ei = (const int*)d_in[1];
    const float* ea = (const float*)d_in[2];
    const float* u = (const float*)d_in[3];
    const int* batch = (const int*)d_in[4];

    const float* eW1 = (const float*)d_in[5];
    const float* eb1 = (const float*)d_in[6];
    const float* eW2 = (const float*)d_in[7];
    const float* eb2 = (const float*)d_in[8];
    const float* egm = (const float*)d_in[9];
    const float* ebt = (const float*)d_in[10];
    const float* n1W1 = (const float*)d_in[11];
    const float* n1b1 = (const float*)d_in[12];
    const float* n1W2 = (const float*)d_in[13];
    const float* n1b2 = (const float*)d_in[14];
    const float* n1g = (const float*)d_in[15];
    const float* n1bt = (const float*)d_in[16];
    const float* n2W1 = (const float*)d_in[17];
    const float* n2b1 = (const float*)d_in[18];
    const float* n2W2 = (const float*)d_in[19];
    const float* n2b2 = (const float*)d_in[20];
    const float* n2g = (const float*)d_in[21];
    const float* n2bt = (const float*)d_in[22];
    const float* gW1 = (const float*)d_in[23];
    const float* gb1 = (const float*)d_in[24];
    const float* gW2 = (const float*)d_in[25];
    const float* gb2 = (const float*)d_in[26];
    const float* gg = (const float*)d_in[27];
    const float* gbt = (const float*)d_in[28];

    float* out = (float*)d_out;
    float* x_out = out;                               // (N, 64)
    float* e_out = out + (size_t)Nn * 64;             // (E, 64)
    float* u_out = out + (size_t)(Nn + Ee) * 64;      // (G, 64)

    cudaFuncSetAttribute(edge_node1_kernel, cudaFuncAttributeMaxDynamicSharedMemorySize, E_SMEM_BYTES);
    cudaFuncSetAttribute(node2_kernel, cudaFuncAttributeMaxDynamicSharedMemorySize, N_SMEM_BYTES);
    cudaFuncSetAttribute(glob_kernel, cudaFuncAttributeMaxDynamicSharedMemorySize, N_SMEM_BYTES);

    zero_kernel<<<2048, 256>>>();
    edge_node1_kernel<<<1184, 512, E_SMEM_BYTES>>>(
        x, ei, ea, u, batch,
        eW1, eb1, eW2, eb2, egm, ebt,
        n1W1, n1b1, n1W2, n1b2, n1g, n1bt,
        e_out);
    node2_kernel<<<1563, 512, N_SMEM_BYTES>>>(
        u, batch, n2W1, n2b1, n2W2, n2b2, n2g, n2bt, x_out);
    glob_kernel<<<1, 512, N_SMEM_BYTES>>>(
        u, gW1, gb1, gW2, gb2, gg, gbt, u_out);
}

// round 11
// speedup vs baseline: 2.1339x; 2.1339x over previous
#include <cuda_runtime.h>

#define Hdim 64
#define Nn   100000
#define Ee   1000000
#define Gg   64

typedef unsigned long long u64;

#define SWZ(k) ((((k) >> 4) & 3) << 3)

// ---------------- scratch (static device arrays: no allocation) ----------------
__device__ float g_aggsum[Nn * Hdim];
__device__ float g_aggcnt[Nn];
__device__ float g_gsum[Gg * Hdim];
__device__ float g_gcnt[Gg];
__device__ float g_PUe[Gg * Hdim];    // u @ eW1d
__device__ float g_PUn2[Gg * Hdim];   // u @ n2W1b + n2b1
__device__ float g_P1p[Nn * Hdim];    // x @ eW1a + PUe[batch] + eb1
__device__ float g_P2Q[Nn * 2 * Hdim];// [x @ eW1b | x @ nW1a + nb1]

// ---------------- packed f32x2 helpers ----------------
__device__ __forceinline__ u64 bcast2(float x) {
    u64 r; unsigned xi = __float_as_uint(x);
    asm("mov.b64 %0, {%1, %2};" : "=l"(r) : "r"(xi), "r"(xi));
    return r;
}
__device__ __forceinline__ void ffma2(u64& d, u64 a, u64 b) {
    asm("fma.rn.f32x2 %0, %1, %2, %0;" : "+l"(d) : "l"(a), "l"(b));
}
__device__ __forceinline__ float2 unpack2(u64 v) {
    unsigned lo, hi;
    asm("mov.b64 {%0, %1}, %2;" : "=r"(lo), "=r"(hi) : "l"(v));
    return make_float2(__uint_as_float(lo), __uint_as_float(hi));
}
__device__ __forceinline__ float fsel(float4 v, int i) {
    return i == 0 ? v.x : (i == 1 ? v.y : (i == 2 ? v.z : v.w));
}

__device__ __forceinline__ float gelu_f(float v) {
    return 0.5f * v * (1.0f + erff(v * 0.7071067811865476f));
}

__device__ __forceinline__ void zero8(u64 (&a)[4][2]) {
#pragma unroll
    for (int i = 0; i < 4; ++i) { a[i][0] = 0ULL; a[i][1] = 0ULL; }
}

template <int NT>
__device__ __forceinline__ void cp_smem(float* dst, const float* src, int nfloats, int tid) {
    const float4* s4 = (const float4*)src;
    float4* d4 = (float4*)dst;
    for (int i = tid; i < (nfloats >> 2); i += NT) d4[i] = s4[i];
}

// type-A GEMM (4i x 4j packed): X k-major in smem, stride 68, e-index XOR-swizzled by SWZ(k)
template <int K, int KB>
__device__ __forceinline__ void gemmA2(const float* __restrict__ Xs, const float* __restrict__ Ws,
                                       int i4, int j4, u64 (&a)[4][2]) {
#pragma unroll 4
    for (int k = 0; k < K; ++k) {
        int kk = KB + k;
        float4 xv = *(const float4*)(Xs + kk * 68 + (i4 ^ SWZ(kk)));
        ulonglong2 wv = *(const ulonglong2*)(Ws + k * 64 + j4);
        u64 x0 = bcast2(xv.x), x1 = bcast2(xv.y), x2 = bcast2(xv.z), x3 = bcast2(xv.w);
        ffma2(a[0][0], x0, wv.x); ffma2(a[0][1], x0, wv.y);
        ffma2(a[1][0], x1, wv.x); ffma2(a[1][1], x1, wv.y);
        ffma2(a[2][0], x2, wv.x); ffma2(a[2][1], x2, wv.y);
        ffma2(a[3][0], x3, wv.x); ffma2(a[3][1], x3, wv.y);
    }
}

// type-B GEMM (4i x 4j packed): H row-major in smem (stride 68), float4 loads along k
template <int K>
__device__ __forceinline__ void gemmB2(const float* __restrict__ Hs, const float* __restrict__ Ws,
                                       int i4, int j4, u64 (&a)[4][2]) {
#pragma unroll 2
    for (int k0 = 0; k0 < K; k0 += 4) {
        float4 h0 = *(const float4*)(Hs + (i4 + 0) * 68 + k0);
        float4 h1 = *(const float4*)(Hs + (i4 + 1) * 68 + k0);
        float4 h2 = *(const float4*)(Hs + (i4 + 2) * 68 + k0);
        float4 h3 = *(const float4*)(Hs + (i4 + 3) * 68 + k0);
#pragma unroll
        for (int dk = 0; dk < 4; ++dk) {
            ulonglong2 wv = *(const ulonglong2*)(Ws + (k0 + dk) * 64 + j4);
            u64 x0 = bcast2(fsel(h0, dk));
            u64 x1 = bcast2(fsel(h1, dk));
            u64 x2 = bcast2(fsel(h2, dk));
            u64 x3 = bcast2(fsel(h3, dk));
            ffma2(a[0][0], x0, wv.x); ffma2(a[0][1], x0, wv.y);
            ffma2(a[1][0], x1, wv.x); ffma2(a[1][1], x1, wv.y);
            ffma2(a[2][0], x2, wv.x); ffma2(a[2][1], x2, wv.y);
            ffma2(a[3][0], x3, wv.x); ffma2(a[3][1], x3, wv.y);
        }
    }
}

// bias(broadcast) + GELU -> H row-major
__device__ __forceinline__ void storeH2(float* __restrict__ Hs, int i4, int j4,
                                        u64 (&a)[4][2], const float* __restrict__ bias) {
    float4 b = *(const float4*)(bias + j4);
#pragma unroll
    for (int r = 0; r < 4; ++r) {
        float2 p0 = unpack2(a[r][0]);
        float2 p1 = unpack2(a[r][1]);
        float* row = Hs + (i4 + r) * 68 + j4;
        row[0] = gelu_f(p0.x + b.x);
        row[1] = gelu_f(p0.y + b.y);
        row[2] = gelu_f(p1.x + b.z);
        row[3] = gelu_f(p1.y + b.w);
    }
}

// per-row offset(register) + GELU -> H row-major
__device__ __forceinline__ void storeH2off(float* __restrict__ Hs, int i4, int j4,
                                           u64 (&a)[4][2], const float4* __restrict__ off) {
#pragma unroll
    for (int r = 0; r < 4; ++r) {
        float2 p0 = unpack2(a[r][0]);
        float2 p1 = unpack2(a[r][1]);
        float* row = Hs + (i4 + r) * 68 + j4;
        row[0] = gelu_f(p0.x + off[r].x);
        row[1] = gelu_f(p0.y + off[r].y);
        row[2] = gelu_f(p1.x + off[r].z);
        row[3] = gelu_f(p1.y + off[r].w);
    }
}

// per-row LayerNorm stats over 64 cols of row-major H
__device__ __forceinline__ void ln_stats(const float* __restrict__ Hs, float* __restrict__ st, int tid) {
    if (tid < 64) {
        float s = 0.0f, s2 = 0.0f;
#pragma unroll
        for (int c = 0; c < 16; ++c) {
            float4 v = *(const float4*)(Hs + tid * 68 + 4 * c);
            s += v.x + v.y + v.z + v.w;
            s2 += v.x * v.x + v.y * v.y + v.z * v.z + v.w * v.w;
        }
        float m = s * (1.0f / 64.0f);
        float var = s2 * (1.0f / 64.0f) - m * m;
        st[tid] = m;
        st[64 + tid] = rsqrtf(fmaxf(var, 0.0f) + 1e-5f);
    }
}

__device__ __forceinline__ void red_v4(float* p, float4 v) {
    asm volatile("red.global.add.v4.f32 [%0], {%1,%2,%3,%4};"
                 :: "l"(p), "f"(v.x), "f"(v.y), "f"(v.z), "f"(v.w) : "memory");
}

// ---------------- zero scratch ----------------
__global__ void zero_kernel() {
    int total = Nn * Hdim + Nn + Gg * Hdim + Gg;
    for (int i = blockIdx.x * blockDim.x + threadIdx.x; i < total; i += gridDim.x * blockDim.x) {
        if (i < Nn * Hdim) g_aggsum[i] = 0.0f;
        else if (i < Nn * Hdim + Nn) g_aggcnt[i - Nn * Hdim] = 0.0f;
        else if (i < Nn * Hdim + Nn + Gg * Hdim) g_gsum[i - Nn * Hdim - Nn] = 0.0f;
        else g_gcnt[i - Nn * Hdim - Nn - Gg * Hdim] = 0.0f;
    }
}

// ---------------- P0: per-graph precompute PUe = u@eW1d, PUn2 = u@n2W1b + n2b1 ----------------
__global__ __launch_bounds__(256, 1) void pu_kernel(
    const float* __restrict__ u, const float* __restrict__ eW1,
    const float* __restrict__ n2W1, const float* __restrict__ n2b1) {
    __shared__ float su[4096], sw1[4096], sw2[4096];
    int tid = threadIdx.x;
    cp_smem<256>(su, u, 4096, tid);
    cp_smem<256>(sw1, eW1 + 192 * 64, 4096, tid);   // eW1d
    cp_smem<256>(sw2, n2W1 + 64 * 64, 4096, tid);   // n2W1b
    __syncthreads();
    int g = tid >> 2, q = tid & 3;
#pragma unroll 4
    for (int jj = 0; jj < 16; ++jj) {
        int j = q * 16 + jj;
        float s1 = 0.0f, s2 = 0.0f;
#pragma unroll 4
        for (int k = 0; k < 64; ++k) {
            float uv = su[g * 64 + k];
            s1 += uv * sw1[k * 64 + j];
            s2 += uv * sw2[k * 64 + j];
        }
        g_PUe[g * 64 + j] = s1;
        g_PUn2[g * 64 + j] = s2 + n2b1[j];
    }
}

// ---------------- P1: per-node precompute P1p, P2, Q ----------------
#define P_OWA 0
#define P_OWB 4096
#define P_OWQ 8192
#define P_OBp 12288
#define P_OX  12416
#define P_SBT 16768
#define P_SMEM_BYTES (16832 * 4)

__global__ __launch_bounds__(256, 2) void node_pre_kernel(
    const float* __restrict__ x, const int* __restrict__ batch,
    const float* __restrict__ eW1, const float* __restrict__ eb1,
    const float* __restrict__ nW1, const float* __restrict__ nb1) {
    extern __shared__ float sm[];
    int tid = threadIdx.x;
    cp_smem<256>(sm + P_OWA, eW1, 4096, tid);            // eW1a (rows 0..63)
    cp_smem<256>(sm + P_OWB, eW1 + 4096, 4096, tid);     // eW1b (rows 64..127)
    cp_smem<256>(sm + P_OWQ, nW1, 4096, tid);            // nW1a (rows 0..63)
    if (tid < 64) { sm[P_OBp + tid] = eb1[tid]; sm[P_OBp + 64 + tid] = nb1[tid]; }
    __syncthreads();

    const int i4 = (tid >> 4) << 2;
    const int j4 = (tid & 15) << 2;
    int* sbt = (int*)(sm + P_SBT);
    int t = blockIdx.x;

    // gather x tile k-major
    {
        int e = tid >> 2, q = tid & 3;
        int n = t * 64 + e;
        bool valid = n < Nn;
        if (q == 0) sbt[e] = valid ? batch[n] : 0;
#pragma unroll
        for (int tt = 0; tt < 4; ++tt) {
            int k0 = q * 16 + tt * 4;
            float4 v = make_float4(0.f, 0.f, 0.f, 0.f);
            if (valid) v = ((const float4*)(x + (size_t)n * 64))[k0 >> 2];
            float* d = sm + P_OX + k0 * 68 + (e ^ SWZ(k0));
            d[0] = v.x; d[68] = v.y; d[136] = v.z; d[204] = v.w;
        }
    }
    __syncthreads();

    u64 acc[4][2];
    // P1p = x@W1a + PUe[batch] + eb1  (pre-activation, no gelu)
    zero8(acc);
    gemmA2<64, 0>(sm + P_OX, sm + P_OWA, i4, j4, acc);
#pragma unroll
    for (int r = 0; r < 4; ++r) {
        int n2 = t * 64 + i4 + r;
        if (n2 < Nn) {
            int b = sbt[i4 + r];
            float4 pu = *(const float4*)(g_PUe + b * 64 + j4);
            float4 b1 = *(const float4*)(sm + P_OBp + j4);
            float2 p0 = unpack2(acc[r][0]);
            float2 p1 = unpack2(acc[r][1]);
            float4 o = make_float4(p0.x + pu.x + b1.x, p0.y + pu.y + b1.y,
                                   p1.x + pu.z + b1.z, p1.y + pu.w + b1.w);
            *(float4*)(g_P1p + (size_t)n2 * 64 + j4) = o;
        }
    }
    // P2 = x@W1b
    zero8(acc);
    gemmA2<64, 0>(sm + P_OX, sm + P_OWB, i4, j4, acc);
#pragma unroll
    for (int r = 0; r < 4; ++r) {
        int n2 = t * 64 + i4 + r;
        if (n2 < Nn) {
            float2 p0 = unpack2(acc[r][0]);
            float2 p1 = unpack2(acc[r][1]);
            *(float4*)(g_P2Q + (size_t)n2 * 128 + j4) = make_float4(p0.x, p0.y, p1.x, p1.y);
        }
    }
    // Q = x@nW1a + nb1
    zero8(acc);
    gemmA2<64, 0>(sm + P_OX, sm + P_OWQ, i4, j4, acc);
#pragma unroll
    for (int r = 0; r < 4; ++r) {
        int n2 = t * 64 + i4 + r;
        if (n2 < Nn) {
            float4 b1 = *(const float4*)(sm + P_OBp + 64 + j4);
            float2 p0 = unpack2(acc[r][0]);
            float2 p1 = unpack2(acc[r][1]);
            *(float4*)(g_P2Q + (size_t)n2 * 128 + 64 + j4) =
                make_float4(p0.x + b1.x, p0.y + b1.y, p1.x + b1.z, p1.y + b1.w);
        }
    }
}

// ---------------- kernel 1: fused edge+message MLPs (decomposed, 256 thr, 2 CTA/SM) ----------------
#define E_OW1C 0
#define E_OW2  4096
#define E_ONB  8192
#define E_ON2  12288
#define E_OBS  16384
#define E_OK   16768
#define E_OH   21120
#define E_OST  25472
#define E_OIDX 25600
#define E_SMEM_BYTES (25728 * 4)

__global__ __launch_bounds__(256, 2) void edge_node1_kernel(
    const int* __restrict__ ei, const float* __restrict__ ea,
    const float* __restrict__ eW1, const float* __restrict__ eb2v,
    const float* __restrict__ eW2, const float* __restrict__ egm,
    const float* __restrict__ ebt,
    const float* __restrict__ nW1, const float* __restrict__ nW2,
    const float* __restrict__ nb2v, const float* __restrict__ ngm,
    const float* __restrict__ nbt,
    float* __restrict__ edge_out) {
    extern __shared__ float sm[];
    int tid = threadIdx.x;
    cp_smem<256>(sm + E_OW1C, eW1 + 8192, 4096, tid);   // eW1c (rows 128..191)
    cp_smem<256>(sm + E_OW2, eW2, 4096, tid);
    cp_smem<256>(sm + E_ONB, nW1 + 4096, 4096, tid);    // nW1b (rows 64..127)
    cp_smem<256>(sm + E_ON2, nW2, 4096, tid);
    if (tid < 64) {
        sm[E_OBS + tid] = eb2v[tid];        sm[E_OBS + 64 + tid] = egm[tid];
        sm[E_OBS + 128 + tid] = ebt[tid];   sm[E_OBS + 192 + tid] = nb2v[tid];
        sm[E_OBS + 256 + tid] = ngm[tid];   sm[E_OBS + 320 + tid] = nbt[tid];
    }
    __syncthreads();

    const int i4 = (tid >> 4) << 2;
    const int j4 = (tid & 15) << 2;
    int* sidx = (int*)(sm + E_OIDX);

    for (int t = blockIdx.x; t < Ee / 64; t += gridDim.x) {
        // indices + aggcnt
        if (tid < 64) {
            int eg_ = t * 64 + tid;
            int r = ei[eg_], c = ei[Ee + eg_];
            sidx[tid] = r; sidx[64 + tid] = c;
            atomicAdd(&g_aggcnt[r], 1.0f);
        }
        // ea gather -> k-major swizzled
        {
            int e = tid >> 2, q = tid & 3;
            const float4* s4 = (const float4*)(ea + (size_t)(t * 64 + e) * 64);
#pragma unroll
            for (int tt = 0; tt < 4; ++tt) {
                int k0 = q * 16 + tt * 4;
                float4 v = s4[k0 >> 2];
                float* d = sm + E_OK + k0 * 68 + (e ^ SWZ(k0));
                d[0] = v.x; d[68] = v.y; d[136] = v.z; d[204] = v.w;
            }
        }
        __syncthreads();

        // per-row offsets into registers
        float4 off1[4], off2[4];
#pragma unroll
        for (int r = 0; r < 4; ++r) {
            int row = sidx[i4 + r], col = sidx[64 + i4 + r];
            float4 a1 = *(const float4*)(g_P1p + (size_t)row * 64 + j4);
            float4 a2 = *(const float4*)(g_P2Q + (size_t)col * 128 + j4);
            off1[r] = make_float4(a1.x + a2.x, a1.y + a2.y, a1.z + a2.z, a1.w + a2.w);
            off2[r] = *(const float4*)(g_P2Q + (size_t)col * 128 + 64 + j4);
        }

        u64 acc[4][2];
        // edge layer1: ea@W1c + off1 (includes x/u parts + eb1) -> gelu -> H
        zero8(acc);
        gemmA2<64, 0>(sm + E_OK, sm + E_OW1C, i4, j4, acc);
        storeH2off(sm + E_OH, i4, j4, acc, off1);
        __syncthreads();
        // edge layer2
        zero8(acc);
        gemmB2<64>(sm + E_OH, sm + E_OW2, i4, j4, acc);
        __syncthreads();
        storeH2(sm + E_OH, i4, j4, acc, sm + E_OBS + 0);
        __syncthreads();
        ln_stats(sm + E_OH, sm + E_OST, tid);
        __syncthreads();
        // LN -> edge_attr_new: write global + k-major into E_OK (overwrite ea)
        {
            int j = tid & 63, g2 = tid >> 6;
            float gj = sm[E_OBS + 64 + j], bj = sm[E_OBS + 128 + j];
            float* ebase = edge_out + (size_t)t * 64 * 64;
#pragma unroll
            for (int r = 0; r < 16; ++r) {
                int e = g2 * 16 + r;
                float v = sm[E_OH + e * 68 + j];
                float nv = (v - sm[E_OST + e]) * sm[E_OST + 64 + e] * gj + bj;
                sm[E_OK + j * 68 + (e ^ SWZ(j))] = nv;
                ebase[(size_t)e * 64 + j] = nv;
            }
        }
        __syncthreads();
        // message layer1: ean@nW1b + off2 (includes x[col]@nW1a + nb1)
        zero8(acc);
        gemmA2<64, 0>(sm + E_OK, sm + E_ONB, i4, j4, acc);
        storeH2off(sm + E_OH, i4, j4, acc, off2);
        __syncthreads();
        // message layer2
        zero8(acc);
        gemmB2<64>(sm + E_OH, sm + E_ON2, i4, j4, acc);
        __syncthreads();
        storeH2(sm + E_OH, i4, j4, acc, sm + E_OBS + 192);
        __syncthreads();
        ln_stats(sm + E_OH, sm + E_OST, tid);
        __syncthreads();
        // LN + scatter into aggsum[row]
        {
            float4 g4 = *(const float4*)(sm + E_OBS + 256 + j4);
            float4 b4 = *(const float4*)(sm + E_OBS + 320 + j4);
#pragma unroll
            for (int ebk = 0; ebk < 4; ++ebk) {
                int e = (tid >> 4) + (ebk << 4);
                float mn = sm[E_OST + e], rs = sm[E_OST + 64 + e];
                float4 v = *(const float4*)(sm + E_OH + e * 68 + j4);
                v.x = (v.x - mn) * rs * g4.x + b4.x;
                v.y = (v.y - mn) * rs * g4.y + b4.y;
                v.z = (v.z - mn) * rs * g4.z + b4.z;
                v.w = (v.w - mn) * rs * g4.w + b4.w;
                red_v4(g_aggsum + (size_t)sidx[e] * 64 + j4, v);
            }
        }
        __syncthreads();
    }
}

// ---------------- kernel 2: node update (decomposed K=64) ----------------
#define N_OW1 0
#define N_OW2 4096
#define N_OB  8192
#define N_OX  8384
#define N_OH  12736
#define N_OST 17088
#define N_OBI 17216
#define N_SMEM_BYTES (17280 * 4)

__global__ __launch_bounds__(256, 2) void node2_kernel(
    const int* __restrict__ batch,
    const float* __restrict__ W1, const float* __restrict__ W2,
    const float* __restrict__ b2, const float* __restrict__ gm,
    const float* __restrict__ bt,
    float* __restrict__ x_out) {
    extern __shared__ float sm[];
    int tid = threadIdx.x;
    cp_smem<256>(sm + N_OW1, W1, 4096, tid);   // n2W1a (rows 0..63)
    cp_smem<256>(sm + N_OW2, W2, 4096, tid);
    if (tid < 64) {
        sm[N_OB + tid] = b2[tid]; sm[N_OB + 64 + tid] = gm[tid]; sm[N_OB + 128 + tid] = bt[tid];
    }
    __syncthreads();
    const int i4 = (tid >> 4) << 2;
    const int j4 = (tid & 15) << 2;
    int* sbi = (int*)(sm + N_OBI);
    const int nTiles = (Nn + 63) / 64;

    for (int t = blockIdx.x; t < nTiles; t += gridDim.x) {
        {
            int e = tid >> 2, q = tid & 3;
            int n = t * 64 + e;
            bool valid = n < Nn;
            if (q == 0) {
                int b = valid ? batch[n] : 0;
                sbi[e] = b;
                if (valid) atomicAdd(&g_gcnt[b], 1.0f);
            }
            float inv = valid ? 1.0f / fmaxf(g_aggcnt[n], 1.0f) : 1.0f;
#pragma unroll
            for (int tt = 0; tt < 4; ++tt) {
                int k0 = q * 16 + tt * 4;
                float4 v = make_float4(0.f, 0.f, 0.f, 0.f);
                if (valid) {
                    v = ((const float4*)(g_aggsum + (size_t)n * 64))[k0 >> 2];
                    v.x *= inv; v.y *= inv; v.z *= inv; v.w *= inv;
                }
                float* d = sm + N_OX + k0 * 68 + (e ^ SWZ(k0));
                d[0] = v.x; d[68] = v.y; d[136] = v.z; d[204] = v.w;
            }
        }
        __syncthreads();
        // offsets: PUn2[batch[n]] (includes u-part + n2b1)
        float4 off[4];
#pragma unroll
        for (int r = 0; r < 4; ++r) {
            int n2 = t * 64 + i4 + r;
            off[r] = make_float4(0.f, 0.f, 0.f, 0.f);
            if (n2 < Nn) off[r] = *(const float4*)(g_PUn2 + sbi[i4 + r] * 64 + j4);
        }
        u64 acc[4][2];
        zero8(acc);
        gemmA2<64, 0>(sm + N_OX, sm + N_OW1, i4, j4, acc);
        storeH2off(sm + N_OH, i4, j4, acc, off);
        __syncthreads();
        zero8(acc);
        gemmB2<64>(sm + N_OH, sm + N_OW2, i4, j4, acc);
        __syncthreads();
        storeH2(sm + N_OH, i4, j4, acc, sm + N_OB);
        __syncthreads();
        ln_stats(sm + N_OH, sm + N_OST, tid);
        __syncthreads();
        {
            int j = tid & 63, g2 = tid >> 6;
            float gj = sm[N_OB + 64 + j], bj = sm[N_OB + 128 + j];
#pragma unroll
            for (int r = 0; r < 16; ++r) {
                int e = g2 * 16 + r;
                int n = t * 64 + e;
                float v = sm[N_OH + e * 68 + j];
                float nv = (v - sm[N_OST + e]) * sm[N_OST + 64 + e] * gj + bj;
                sm[N_OH + e * 68 + j] = nv;
                if (n < Nn) x_out[(size_t)n * 64 + j] = nv;
            }
        }
        __syncthreads();
        {
#pragma unroll
            for (int ebk = 0; ebk < 4; ++ebk) {
                int e = (tid >> 4) + (ebk << 4);
                int n = t * 64 + e;
                if (n < Nn) {
                    float4 v = *(const float4*)(sm + N_OH + e * 68 + j4);
                    red_v4(g_gsum + (size_t)sbi[e] * 64 + j4, v);
                }
            }
        }
        __syncthreads();
    }
}

// ---------------- kernel 3: global MLP ----------------
#define G_OW1 0
#define G_OW2 8192
#define G_OB  12288
#define G_OX  12544
#define G_OH  16896
#define G_OST 21248
#define G_SMEM_BYTES (21376 * 4)

__global__ __launch_bounds__(256, 1) void glob_kernel(
    const float* __restrict__ u,
    const float* __restrict__ W1, const float* __restrict__ b1,
    const float* __restrict__ W2, const float* __restrict__ b2,
    const float* __restrict__ gm, const float* __restrict__ bt,
    float* __restrict__ u_out) {
    extern __shared__ float sm[];
    int tid = threadIdx.x;
    cp_smem<256>(sm + G_OW1, W1, 8192, tid);
    cp_smem<256>(sm + G_OW2, W2, 4096, tid);
    if (tid < 64) {
        sm[G_OB + tid] = b1[tid];       sm[G_OB + 64 + tid] = b2[tid];
        sm[G_OB + 128 + tid] = gm[tid]; sm[G_OB + 192 + tid] = bt[tid];
    }
    __syncthreads();
    const int i4 = (tid >> 4) << 2;
    const int j4 = (tid & 15) << 2;
    {
        int e = tid >> 2, q = tid & 3;
        float inv = 1.0f / fmaxf(g_gcnt[e], 1.0f);
#pragma unroll
        for (int tt = 0; tt < 8; ++tt) {
            int k0 = q * 32 + tt * 4;
            float4 v;
            if (k0 < 64) {
                v = ((const float4*)(u + (size_t)e * 64))[k0 >> 2];
            } else {
                v = ((const float4*)(g_gsum + (size_t)e * 64))[(k0 - 64) >> 2];
                v.x *= inv; v.y *= inv; v.z *= inv; v.w *= inv;
            }
            float* d = sm + G_OX + k0 * 68 + (e ^ SWZ(k0));
            d[0] = v.x; d[68] = v.y; d[136] = v.z; d[204] = v.w;
        }
    }
    __syncthreads();
    u64 acc[4][2];
    zero8(acc);
    gemmA2<128, 0>(sm + G_OX, sm + G_OW1, i4, j4, acc);
    storeH2(sm + G_OH, i4, j4, acc, sm + G_OB);
    __syncthreads();
    zero8(acc);
    gemmB2<64>(sm + G_OH, sm + G_OW2, i4, j4, acc);
    __syncthreads();
    storeH2(sm + G_OH, i4, j4, acc, sm + G_OB + 64);
    __syncthreads();
    ln_stats(sm + G_OH, sm + G_OST, tid);
    __syncthreads();
    {
        int j = tid & 63, g2 = tid >> 6;
        float gj = sm[G_OB + 128 + j], bj = sm[G_OB + 192 + j];
#pragma unroll
        for (int r = 0; r < 16; ++r) {
            int e = g2 * 16 + r;
            float v = sm[G_OH + e * 68 + j];
            float nv = (v - sm[G_OST + e]) * sm[G_OST + 64 + e] * gj + bj;
            u_out[(size_t)e * 64 + j] = nv;
        }
    }
}

// ---------------- launch ----------------
extern "C" void kernel_launch(void* const* d_in, const int* in_sizes, int n_in,
                              void* d_out, int out_size) {
    const float* x = (const float*)d_in[0];
    const int* ei = (const int*)d_in[1];
    const float* ea = (const float*)d_in[2];
    const float* u = (const float*)d_in[3];
    const int* batch = (const int*)d_in[4];

    const float* eW1 = (const float*)d_in[5];
    const float* eb1 = (const float*)d_in[6];
    const float* eW2 = (const float*)d_in[7];
    const float* eb2 = (const float*)d_in[8];
    const float* egm = (const float*)d_in[9];
    const float* ebt = (const float*)d_in[10];
    const float* n1W1 = (const float*)d_in[11];
    const float* n1b1 = (const float*)d_in[12];
    const float* n1W2 = (const float*)d_in[13];
    const float* n1b2 = (const float*)d_in[14];
    const float* n1g = (const float*)d_in[15];
    const float* n1bt = (const float*)d_in[16];
    const float* n2W1 = (const float*)d_in[17];
    const float* n2b1 = (const float*)d_in[18];
    const float* n2W2 = (const float*)d_in[19];
    const float* n2b2 = (const float*)d_in[20];
    const float* n2g = (const float*)d_in[21];
    const float* n2bt = (const float*)d_in[22];
    const float* gW1 = (const float*)d_in[23];
    const float* gb1 = (const float*)d_in[24];
    const float* gW2 = (const float*)d_in[25];
    const float* gb2 = (const float*)d_in[26];
    const float* gg = (const float*)d_in[27];
    const float* gbt = (const float*)d_in[28];

    float* out = (float*)d_out;
    float* x_out = out;                               // (N, 64)
    float* e_out = out + (size_t)Nn * 64;             // (E, 64)
    float* u_out = out + (size_t)(Nn + Ee) * 64;      // (G, 64)

    cudaFuncSetAttribute(node_pre_kernel, cudaFuncAttributeMaxDynamicSharedMemorySize, P_SMEM_BYTES);
    cudaFuncSetAttribute(edge_node1_kernel, cudaFuncAttributeMaxDynamicSharedMemorySize, E_SMEM_BYTES);
    cudaFuncSetAttribute(node2_kernel, cudaFuncAttributeMaxDynamicSharedMemorySize, N_SMEM_BYTES);
    cudaFuncSetAttribute(glob_kernel, cudaFuncAttributeMaxDynamicSharedMemorySize, G_SMEM_BYTES);

    zero_kernel<<<2048, 256>>>();
    pu_kernel<<<1, 256>>>(u, eW1, n2W1, n2b1);
    node_pre_kernel<<<(Nn + 63) / 64, 256, P_SMEM_BYTES>>>(x, batch, eW1, eb1, n1W1, n1b1);
    edge_node1_kernel<<<2368, 256, E_SMEM_BYTES>>>(
        ei, ea, eW1, eb2, eW2, egm, ebt,
        n1W1, n1W2, n1b2, n1g, n1bt,
        e_out);
    node2_kernel<<<1184, 256, N_SMEM_BYTES>>>(
        batch, n2W1, n2W2, n2b2, n2g, n2bt, x_out);
    glob_kernel<<<1, 256, G_SMEM_BYTES>>>(
        u, gW1, gb1, gW2, gb2, gg, gbt, u_out);
}